// round 4
// baseline (speedup 1.0000x reference)
#include <cuda_runtime.h>
#include <cuda_fp16.h>

#define BATCH  512
#define TSTEPS 256
#define IDIM   32
#define HDIM   128
#define GDIM   512                    // 4*H
#define MROWS  (BATCH * TSTEPS)       // 131072

typedef unsigned long long ull;

// ---------------- scratch (static device globals: allocation-free) ----------
__device__ float  g_xg[(size_t)MROWS * GDIM];   // 256 MB, reused for xg0 then xg1
__device__ float  g_h0[(size_t)MROWS * HDIM];   // 64 MB, layer-0 hidden states
__device__ float  g_h1last[BATCH * HDIM];       // last hidden of layer 1
__device__ __half g_whh[2 * GDIM * HDIM];       // fp16 copies of w_hh0, w_hh1

// ---------------- f32x2 helpers (FFMA2 — PTX-only on sm_103a) ---------------
__device__ __forceinline__ ull pack2(float x, float y) {
    ull r; asm("mov.b64 %0, {%1, %2};" : "=l"(r) : "f"(x), "f"(y)); return r;
}
__device__ __forceinline__ void unpack2(ull v, float &x, float &y) {
    asm("mov.b64 {%0, %1}, %2;" : "=f"(x), "=f"(y) : "l"(v));
}
__device__ __forceinline__ void ffma2(ull &d, ull a, ull b) {
    asm("fma.rn.f32x2 %0, %1, %2, %0;" : "+l"(d) : "l"(a), "l"(b));
}

// ---------------- fast transcendentals (flag-independent, ~ulp accurate) ----
__device__ __forceinline__ float ex2f(float x) {
    float y; asm("ex2.approx.f32 %0, %1;" : "=f"(y) : "f"(x)); return y;
}
__device__ __forceinline__ float rcpf(float x) {
    float y; asm("rcp.approx.f32 %0, %1;" : "=f"(y) : "f"(x)); return y;
}
__device__ __forceinline__ float sigmf(float x) {
    return rcpf(1.0f + ex2f(-1.4426950408889634f * x));
}
__device__ __forceinline__ float tanhf_(float x) {
    return 2.0f * sigmf(2.0f * x) - 1.0f;
}

// ---------------- K0: convert recurrent weights to fp16 ---------------------
__global__ void k_convert(const float* __restrict__ w0, const float* __restrict__ w1) {
    int i = blockIdx.x * blockDim.x + threadIdx.x;
    if (i < GDIM * HDIM) {
        g_whh[i]               = __float2half(w0[i]);
        g_whh[GDIM * HDIM + i] = __float2half(w1[i]);
    }
}

// ---------------- K1/K3: C[M,512] = A[M,K] @ W[512,K]^T + b1 + b2 -> g_xg ----
// Tile 64x128, 256 threads, thread = 4 rows x 8 cols (f32x2 col pairs).
__global__ __launch_bounds__(256) void k_gemm(const float* __restrict__ Aext, int useH0,
                                              const float* __restrict__ W,
                                              const float* __restrict__ b1,
                                              const float* __restrict__ b2, int K) {
    extern __shared__ float sm[];
    float* aT = sm;              // [K][68]  (transposed A tile, pad 4 keeps 16B align)
    float* bT = sm + K * 68;     // [K][132]
    const float* A = useH0 ? (const float*)g_h0 : Aext;

    int t = threadIdx.x;
    const float* Ab = A + (size_t)blockIdx.x * 64 * K;
    const float* Wb = W + (size_t)blockIdx.y * 128 * K;
    for (int i = t; i < 64 * K; i += 256)  { int m = i / K, k = i - m * K; aT[k * 68 + m] = Ab[i]; }
    for (int i = t; i < 128 * K; i += 256) { int n = i / K, k = i - n * K; bT[k * 132 + n] = Wb[i]; }
    __syncthreads();

    int tx = t & 15, ty = t >> 4;
    int r0 = ty * 4, c0 = tx * 8;
    ull acc[4][4];
    #pragma unroll
    for (int r = 0; r < 4; r++)
        #pragma unroll
        for (int p = 0; p < 4; p++) acc[r][p] = 0ULL;

    #pragma unroll 4
    for (int k = 0; k < K; k++) {
        float4 a4 = *(const float4*)&aT[k * 68 + r0];
        float4 bA = *(const float4*)&bT[k * 132 + c0];
        float4 bB = *(const float4*)&bT[k * 132 + c0 + 4];
        ull ar[4] = { pack2(a4.x, a4.x), pack2(a4.y, a4.y), pack2(a4.z, a4.z), pack2(a4.w, a4.w) };
        ull bp[4] = { pack2(bA.x, bA.y), pack2(bA.z, bA.w), pack2(bB.x, bB.y), pack2(bB.z, bB.w) };
        #pragma unroll
        for (int r = 0; r < 4; r++) {
            ffma2(acc[r][0], ar[r], bp[0]);
            ffma2(acc[r][1], ar[r], bp[1]);
            ffma2(acc[r][2], ar[r], bp[2]);
            ffma2(acc[r][3], ar[r], bp[3]);
        }
    }

    int gc = blockIdx.y * 128 + c0;
    float bias[8];
    #pragma unroll
    for (int j = 0; j < 8; j++) bias[j] = b1[gc + j] + b2[gc + j];
    size_t rowBase = ((size_t)blockIdx.x * 64 + r0) * GDIM + gc;
    #pragma unroll
    for (int r = 0; r < 4; r++) {
        float o[8];
        unpack2(acc[r][0], o[0], o[1]); unpack2(acc[r][1], o[2], o[3]);
        unpack2(acc[r][2], o[4], o[5]); unpack2(acc[r][3], o[6], o[7]);
        #pragma unroll
        for (int j = 0; j < 8; j++) o[j] += bias[j];
        *(float4*)&g_xg[rowBase + (size_t)r * GDIM]     = make_float4(o[0], o[1], o[2], o[3]);
        *(float4*)&g_xg[rowBase + (size_t)r * GDIM + 4] = make_float4(o[4], o[5], o[6], o[7]);
    }
}

// ---------------- K2/K4: persistent LSTM recurrence -------------------------
// 128 CTAs x 256 threads; CTA owns 4 batch elements for all 256 steps.
// SMEM: wT fp16 [128][512] (128KB) + gates fp32 [4][512] + h fp32 [128][4].
__global__ __launch_bounds__(256) void k_rec(int layer) {
    extern __shared__ char smraw[];
    __half* wT    = (__half*)smraw;                         // [k][row]
    float*  gates = (float*)(smraw + 131072);               // [b][row]
    float4* h4    = (float4*)(smraw + 131072 + 8192);       // [k] -> (b0,b1,b2,b3)

    int t = threadIdx.x;
    const __half* wsrc = g_whh + layer * (GDIM * HDIM);
    for (int i = t; i < GDIM * HDIM; i += 256) {            // transpose load W_hh
        int r = i >> 7, k = i & 127;
        wT[k * GDIM + r] = wsrc[i];
    }
    if (t < HDIM) h4[t] = make_float4(0.f, 0.f, 0.f, 0.f);
    __syncthreads();

    const int r0   = 2 * t;        // this thread's 2 gate rows
    const int b_lo = t >> 7;       // elementwise batch (and b_lo+2)
    const int u    = t & 127;      // elementwise hidden unit
    float c_lo = 0.f, c_hi = 0.f;
    const size_t cta_b = (size_t)blockIdx.x * 4;
    const float* xg_base = g_xg + ((cta_b * TSTEPS) << 9);  // *GDIM

    for (int ts = 0; ts < TSTEPS; ts++) {
        // ---- gates(pre) = h @ W_hh^T for rows r0, r0+1, batches 0..3 ----
        ull a00 = 0, a01 = 0, a10 = 0, a11 = 0;
        #pragma unroll 8
        for (int k = 0; k < HDIM; k++) {
            __half2 w2 = *(const __half2*)&wT[k * GDIM + r0];
            float w0f = __low2float(w2), w1f = __high2float(w2);
            float4 h  = h4[k];
            ull h01 = pack2(h.x, h.y), h23 = pack2(h.z, h.w);
            ull wr0 = pack2(w0f, w0f), wr1 = pack2(w1f, w1f);
            ffma2(a00, wr0, h01); ffma2(a01, wr0, h23);
            ffma2(a10, wr1, h01); ffma2(a11, wr1, h23);
        }
        float v00, v01, v02, v03, v10, v11, v12, v13;
        unpack2(a00, v00, v01); unpack2(a01, v02, v03);   // row r0,   batches 0..3
        unpack2(a10, v10, v11); unpack2(a11, v12, v13);   // row r0+1, batches 0..3

        const float* xgp = xg_base + ((size_t)ts << 9) + r0;
        float2 x0 = *(const float2*)(xgp);
        float2 x1 = *(const float2*)(xgp + (1 << 17));    // + b*T*GDIM
        float2 x2 = *(const float2*)(xgp + (2 << 17));
        float2 x3 = *(const float2*)(xgp + (3 << 17));
        *(float2*)&gates[0 * GDIM + r0] = make_float2(v00 + x0.x, v10 + x0.y);
        *(float2*)&gates[1 * GDIM + r0] = make_float2(v01 + x1.x, v11 + x1.y);
        *(float2*)&gates[2 * GDIM + r0] = make_float2(v02 + x2.x, v12 + x2.y);
        *(float2*)&gates[3 * GDIM + r0] = make_float2(v03 + x3.x, v13 + x3.y);
        __syncthreads();

        // ---- elementwise LSTM cell: this thread owns (b_lo,u) and (b_lo+2,u)
        float* hw = (float*)h4;
        {
            const float* gb = &gates[b_lo * GDIM];
            float gi = sigmf(gb[u]);
            float gf = sigmf(gb[u + 128]);
            float gg = tanhf_(gb[u + 256]);
            float go = sigmf(gb[u + 384]);
            c_lo = gf * c_lo + gi * gg;
            float h = go * tanhf_(c_lo);
            hw[u * 4 + b_lo] = h;
            if (layer == 0)
                g_h0[((cta_b + b_lo) * TSTEPS + ts) * HDIM + u] = h;
            else if (ts == TSTEPS - 1)
                g_h1last[(cta_b + b_lo) * HDIM + u] = h;
        }
        {
            int b = b_lo + 2;
            const float* gb = &gates[b * GDIM];
            float gi = sigmf(gb[u]);
            float gf = sigmf(gb[u + 128]);
            float gg = tanhf_(gb[u + 256]);
            float go = sigmf(gb[u + 384]);
            c_hi = gf * c_hi + gi * gg;
            float h = go * tanhf_(c_hi);
            hw[u * 4 + b] = h;
            if (layer == 0)
                g_h0[((cta_b + b) * TSTEPS + ts) * HDIM + u] = h;
            else if (ts == TSTEPS - 1)
                g_h1last[(cta_b + b) * HDIM + u] = h;
        }
        __syncthreads();
    }
}

// ---------------- K5: FC head  out = relu(h @ fc1^T + b1) @ fc2^T + b2 ------
__global__ void k_fc(const float* __restrict__ w1, const float* __restrict__ b1,
                     const float* __restrict__ w2, const float* __restrict__ b2,
                     float* __restrict__ out) {
    __shared__ float red[2];
    int b = blockIdx.x, j = threadIdx.x;   // 64 threads
    const float* hv = g_h1last + b * HDIM;
    const float* wr = w1 + j * HDIM;
    float acc = b1[j];
    #pragma unroll 4
    for (int k = 0; k < HDIM; k++) acc += hv[k] * wr[k];
    float z = fmaxf(acc, 0.0f) * w2[j];
    #pragma unroll
    for (int off = 16; off > 0; off >>= 1) z += __shfl_down_sync(0xffffffffu, z, off);
    if ((j & 31) == 0) red[j >> 5] = z;
    __syncthreads();
    if (j == 0) out[b] = red[0] + red[1] + b2[0];
}

// ---------------- launch -----------------------------------------------------
extern "C" void kernel_launch(void* const* d_in, const int* in_sizes, int n_in,
                              void* d_out, int out_size) {
    const float* x     = (const float*)d_in[0];
    const float* w_ih0 = (const float*)d_in[1];
    const float* w_hh0 = (const float*)d_in[2];
    const float* b_ih0 = (const float*)d_in[3];
    const float* b_hh0 = (const float*)d_in[4];
    const float* w_ih1 = (const float*)d_in[5];
    const float* w_hh1 = (const float*)d_in[6];
    const float* b_ih1 = (const float*)d_in[7];
    const float* b_hh1 = (const float*)d_in[8];
    const float* fc1_w = (const float*)d_in[9];
    const float* fc1_b = (const float*)d_in[10];
    const float* fc2_w = (const float*)d_in[11];
    const float* fc2_b = (const float*)d_in[12];
    float* out = (float*)d_out;

    cudaFuncSetAttribute(k_gemm, cudaFuncAttributeMaxDynamicSharedMemorySize, 128 * 800);
    cudaFuncSetAttribute(k_rec,  cudaFuncAttributeMaxDynamicSharedMemorySize, 141312);

    k_convert<<<(GDIM * HDIM + 255) / 256, 256>>>(w_hh0, w_hh1);

    dim3 gg(MROWS / 64, 4);
    // xg0 = x @ w_ih0^T + b_ih0 + b_hh0           (K = 32)
    k_gemm<<<gg, 256, 32 * 800>>>(x, 0, w_ih0, b_ih0, b_hh0, 32);
    // layer-0 recurrence (writes g_h0)
    k_rec<<<128, 256, 141312>>>(0);
    // xg1 = h0 @ w_ih1^T + b_ih1 + b_hh1          (K = 128)
    k_gemm<<<gg, 256, 128 * 800>>>(nullptr, 1, w_ih1, b_ih1, b_hh1, 128);
    // layer-1 recurrence (writes g_h1last)
    k_rec<<<128, 256, 141312>>>(1);
    // FC head
    k_fc<<<BATCH, 64>>>(fc1_w, fc1_b, fc2_w, fc2_b, out);
}

// round 5
// speedup vs baseline: 1.1678x; 1.1678x over previous
#include <cuda_runtime.h>
#include <cuda_fp16.h>

#define BATCH  512
#define TSTEPS 256
#define IDIM   32
#define HDIM   128
#define GDIM   512                    // 4*H
#define MROWS  (BATCH * TSTEPS)       // 131072

typedef unsigned long long ull;

// ---------------- scratch (static device globals: allocation-free) ----------
__device__ float  g_xg[(size_t)MROWS * GDIM];   // 256 MB, reused for xg0 then xg1
__device__ float  g_h0[(size_t)MROWS * HDIM];   // 64 MB, layer-0 hidden states
__device__ float  g_h1last[BATCH * HDIM];       // last hidden of layer 1
__device__ __half g_whh[2 * GDIM * HDIM];       // fp16 copies of w_hh0, w_hh1

// ---------------- f32x2 helpers (FFMA2 — PTX-only on sm_103a) ---------------
__device__ __forceinline__ ull pack2(float x, float y) {
    ull r; asm("mov.b64 %0, {%1, %2};" : "=l"(r) : "f"(x), "f"(y)); return r;
}
__device__ __forceinline__ void unpack2(ull v, float &x, float &y) {
    asm("mov.b64 {%0, %1}, %2;" : "=f"(x), "=f"(y) : "l"(v));
}
__device__ __forceinline__ void ffma2(ull &d, ull a, ull b) {
    asm("fma.rn.f32x2 %0, %1, %2, %0;" : "+l"(d) : "l"(a), "l"(b));
}

// ---------------- fast transcendentals ---------------------------------------
__device__ __forceinline__ float ex2f(float x) {
    float y; asm("ex2.approx.f32 %0, %1;" : "=f"(y) : "f"(x)); return y;
}
__device__ __forceinline__ float rcpf(float x) {
    float y; asm("rcp.approx.f32 %0, %1;" : "=f"(y) : "f"(x)); return y;
}
__device__ __forceinline__ float sigmf(float x) {
    return rcpf(1.0f + ex2f(-1.4426950408889634f * x));
}
__device__ __forceinline__ float tanhf_(float x) {
    return 2.0f * sigmf(2.0f * x) - 1.0f;
}

// ---------------- K0: convert recurrent weights to fp16 ---------------------
__global__ void k_convert(const float* __restrict__ w0, const float* __restrict__ w1) {
    int i = blockIdx.x * blockDim.x + threadIdx.x;
    if (i < GDIM * HDIM) {
        g_whh[i]               = __float2half(w0[i]);
        g_whh[GDIM * HDIM + i] = __float2half(w1[i]);
    }
}

// ---------------- K1/K3: C[M,512] = A[M,K] @ W[512,K]^T + b1 + b2 -> g_xg ----
// Tile 128x128, 256 threads, thread = 8 rows x 8 cols (f32x2 col pairs).
// fma-bound: per k, 4 LDS.128 (a-loads warp-broadcast) feed 32 ffma2.
template<int K>
__global__ __launch_bounds__(256) void k_gemm(const float* __restrict__ Aext, int useH0,
                                              const float* __restrict__ W,
                                              const float* __restrict__ b1,
                                              const float* __restrict__ b2) {
    extern __shared__ float sm[];
    float* aT = sm;               // [K][132]  (transposed A tile)
    float* bT = sm + K * 132;     // [K][132]
    const float* A = useH0 ? (const float*)g_h0 : Aext;

    int t = threadIdx.x;
    const float* Ab = A + (size_t)blockIdx.x * 128 * K;
    const float* Wb = W + (size_t)blockIdx.y * 128 * K;
    #pragma unroll 4
    for (int i = t; i < 128 * K; i += 256) { int m = i / K, k = i - m * K; aT[k * 132 + m] = Ab[i]; }
    #pragma unroll 4
    for (int i = t; i < 128 * K; i += 256) { int n = i / K, k = i - n * K; bT[k * 132 + n] = Wb[i]; }
    __syncthreads();

    int tx = t & 15, ty = t >> 4;
    int m0 = ty * 8, n0 = tx * 8;
    ull acc[8][4];
    #pragma unroll
    for (int r = 0; r < 8; r++)
        #pragma unroll
        for (int p = 0; p < 4; p++) acc[r][p] = 0ULL;

    #pragma unroll 4
    for (int k = 0; k < K; k++) {
        float4 aA = *(const float4*)&aT[k * 132 + m0];
        float4 aB = *(const float4*)&aT[k * 132 + m0 + 4];
        float4 bA = *(const float4*)&bT[k * 132 + n0];
        float4 bB = *(const float4*)&bT[k * 132 + n0 + 4];
        ull bp[4] = { pack2(bA.x, bA.y), pack2(bA.z, bA.w), pack2(bB.x, bB.y), pack2(bB.z, bB.w) };
        float ael[8] = { aA.x, aA.y, aA.z, aA.w, aB.x, aB.y, aB.z, aB.w };
        #pragma unroll
        for (int r = 0; r < 8; r++) {
            ull ar = pack2(ael[r], ael[r]);
            ffma2(acc[r][0], ar, bp[0]);
            ffma2(acc[r][1], ar, bp[1]);
            ffma2(acc[r][2], ar, bp[2]);
            ffma2(acc[r][3], ar, bp[3]);
        }
    }

    int gc = blockIdx.y * 128 + n0;
    float bias[8];
    #pragma unroll
    for (int j = 0; j < 8; j++) bias[j] = b1[gc + j] + b2[gc + j];
    size_t rowBase = ((size_t)blockIdx.x * 128 + m0) * GDIM + gc;
    #pragma unroll
    for (int r = 0; r < 8; r++) {
        float o[8];
        unpack2(acc[r][0], o[0], o[1]); unpack2(acc[r][1], o[2], o[3]);
        unpack2(acc[r][2], o[4], o[5]); unpack2(acc[r][3], o[6], o[7]);
        #pragma unroll
        for (int j = 0; j < 8; j++) o[j] += bias[j];
        *(float4*)&g_xg[rowBase + (size_t)r * GDIM]     = make_float4(o[0], o[1], o[2], o[3]);
        *(float4*)&g_xg[rowBase + (size_t)r * GDIM + 4] = make_float4(o[4], o[5], o[6], o[7]);
    }
}

// ---------------- K2/K4: persistent LSTM recurrence -------------------------
// 128 CTAs x 256 threads; CTA owns 4 batch elems for all 256 steps.
// Split-K matmul: thread (half=t>>7, tl=t&127) computes rows tl*4..tl*4+3 for
// all 4 batches over k in [half*64, half*64+64). h stored DUPLICATED in SMEM
// ((h,h) pairs) so FFMA2 accumulates row-pairs with zero dup-movs.
__global__ __launch_bounds__(256) void k_rec(int layer) {
    extern __shared__ char smraw[];
    __half* wT   = (__half*)smraw;                        // [k][row] fp16, 128 KB
    float*  part = (float*)(smraw + 131072);              // [2][4][512] partials, 16 KB
    float*  hdup = (float*)(smraw + 131072 + 16384);      // [128][12] (uses 8/row), 6 KB

    int t = threadIdx.x;
    const __half* wsrc = g_whh + layer * (GDIM * HDIM);
    for (int i = t; i < GDIM * HDIM; i += 256) {          // transpose load W_hh
        int r = i >> 7, k = i & 127;
        wT[k * GDIM + r] = wsrc[i];
    }
    for (int i = t; i < 128 * 12; i += 256) hdup[i] = 0.f;
    __syncthreads();

    const int half = t >> 7, tl = t & 127;
    const int r0 = tl * 4, kb = half * 64;
    const int b_lo = half, u = tl;                        // elementwise role
    float cst[2] = {0.f, 0.f};
    const size_t cta_b = (size_t)blockIdx.x * 4;
    const float* xgb = g_xg + (cta_b << 17);              // cta_b * TSTEPS * GDIM
    float* p_my = part + half * 2048;

    for (int ts = 0; ts < TSTEPS; ts++) {
        // ---- prefetch xg for this thread's 2 cells (overlaps with matmul) --
        const float* xp0 = xgb + ((size_t)b_lo << 17) + (size_t)ts * GDIM + u;
        const float* xp1 = xp0 + ((size_t)2 << 17);
        float xv0[4] = { xp0[0], xp0[128], xp0[256], xp0[384] };
        float xv1[4] = { xp1[0], xp1[128], xp1[256], xp1[384] };

        // ---- partial gates = h @ W_hh^T (rows r0..r0+3, batches 0..3) ------
        ull acc[4][2];
        #pragma unroll
        for (int b = 0; b < 4; b++) { acc[b][0] = 0ULL; acc[b][1] = 0ULL; }

        #pragma unroll 8
        for (int kk = 0; kk < 64; kk++) {
            int k = kb + kk;
            uint2 wr = *(const uint2*)&wT[k * GDIM + r0];          // 4 fp16 weights
            float2 f01 = __half22float2(*(__half2*)&wr.x);          // rows r0, r0+1
            float2 f23 = __half22float2(*(__half2*)&wr.y);          // rows r0+2, r0+3
            ull w01 = pack2(f01.x, f01.y);
            ull w23 = pack2(f23.x, f23.y);
            const float4* hp = (const float4*)(hdup + k * 12);
            float4 h0v = hp[0], h1v = hp[1];                        // (b0,b0,b1,b1),(b2,b2,b3,b3)
            ull hb0 = pack2(h0v.x, h0v.y), hb1 = pack2(h0v.z, h0v.w);
            ull hb2 = pack2(h1v.x, h1v.y), hb3 = pack2(h1v.z, h1v.w);
            ffma2(acc[0][0], w01, hb0); ffma2(acc[0][1], w23, hb0);
            ffma2(acc[1][0], w01, hb1); ffma2(acc[1][1], w23, hb1);
            ffma2(acc[2][0], w01, hb2); ffma2(acc[2][1], w23, hb2);
            ffma2(acc[3][0], w01, hb3); ffma2(acc[3][1], w23, hb3);
        }
        #pragma unroll
        for (int b = 0; b < 4; b++) {
            float lo, hi;
            unpack2(acc[b][0], lo, hi); *(float2*)&p_my[b * 512 + r0]     = make_float2(lo, hi);
            unpack2(acc[b][1], lo, hi); *(float2*)&p_my[b * 512 + r0 + 2] = make_float2(lo, hi);
        }
        __syncthreads();

        // ---- elementwise LSTM cell: cells (b_lo,u) and (b_lo+2,u) ----------
        #pragma unroll
        for (int j = 0; j < 2; j++) {
            int b = b_lo + 2 * j;
            const float* pa = &part[b * 512];
            const float* pb = &part[2048 + b * 512];
            const float* xv = j ? xv1 : xv0;
            float gi = sigmf (pa[u]       + pb[u]       + xv[0]);
            float gf = sigmf (pa[u + 128] + pb[u + 128] + xv[1]);
            float gg = tanhf_(pa[u + 256] + pb[u + 256] + xv[2]);
            float go = sigmf (pa[u + 384] + pb[u + 384] + xv[3]);
            cst[j] = gf * cst[j] + gi * gg;
            float h = go * tanhf_(cst[j]);
            *(float2*)&hdup[u * 12 + 2 * b] = make_float2(h, h);
            if (layer == 0)
                g_h0[((cta_b + b) * TSTEPS + ts) * HDIM + u] = h;
            else if (ts == TSTEPS - 1)
                g_h1last[(cta_b + b) * HDIM + u] = h;
        }
        __syncthreads();
    }
}

// ---------------- K5: FC head  out = relu(h @ fc1^T + b1) @ fc2^T + b2 ------
__global__ void k_fc(const float* __restrict__ w1, const float* __restrict__ b1,
                     const float* __restrict__ w2, const float* __restrict__ b2,
                     float* __restrict__ out) {
    __shared__ float red[2];
    int b = blockIdx.x, j = threadIdx.x;   // 64 threads
    const float* hv = g_h1last + b * HDIM;
    const float* wr = w1 + j * HDIM;
    float acc = b1[j];
    #pragma unroll 4
    for (int k = 0; k < HDIM; k++) acc += hv[k] * wr[k];
    float z = fmaxf(acc, 0.0f) * w2[j];
    #pragma unroll
    for (int off = 16; off > 0; off >>= 1) z += __shfl_down_sync(0xffffffffu, z, off);
    if ((j & 31) == 0) red[j >> 5] = z;
    __syncthreads();
    if (j == 0) out[b] = red[0] + red[1] + b2[0];
}

// ---------------- launch -----------------------------------------------------
extern "C" void kernel_launch(void* const* d_in, const int* in_sizes, int n_in,
                              void* d_out, int out_size) {
    const float* x     = (const float*)d_in[0];
    const float* w_ih0 = (const float*)d_in[1];
    const float* w_hh0 = (const float*)d_in[2];
    const float* b_ih0 = (const float*)d_in[3];
    const float* b_hh0 = (const float*)d_in[4];
    const float* w_ih1 = (const float*)d_in[5];
    const float* w_hh1 = (const float*)d_in[6];
    const float* b_ih1 = (const float*)d_in[7];
    const float* b_hh1 = (const float*)d_in[8];
    const float* fc1_w = (const float*)d_in[9];
    const float* fc1_b = (const float*)d_in[10];
    const float* fc2_w = (const float*)d_in[11];
    const float* fc2_b = (const float*)d_in[12];
    float* out = (float*)d_out;

    const int smem_g128 = 2 * 128 * 132 * 4;   // 135168
    const int smem_g32  = 2 * 32 * 132 * 4;    // 33792
    const int smem_rec  = 131072 + 16384 + 128 * 12 * 4;  // 153600
    cudaFuncSetAttribute(k_gemm<128>, cudaFuncAttributeMaxDynamicSharedMemorySize, smem_g128);
    cudaFuncSetAttribute(k_gemm<32>,  cudaFuncAttributeMaxDynamicSharedMemorySize, smem_g32);
    cudaFuncSetAttribute(k_rec,       cudaFuncAttributeMaxDynamicSharedMemorySize, smem_rec);

    k_convert<<<(GDIM * HDIM + 255) / 256, 256>>>(w_hh0, w_hh1);

    dim3 gg(MROWS / 128, 4);
    // xg0 = x @ w_ih0^T + b_ih0 + b_hh0           (K = 32)
    k_gemm<32><<<gg, 256, smem_g32>>>(x, 0, w_ih0, b_ih0, b_hh0);
    // layer-0 recurrence (writes g_h0)
    k_rec<<<128, 256, smem_rec>>>(0);
    // xg1 = h0 @ w_ih1^T + b_ih1 + b_hh1          (K = 128)
    k_gemm<128><<<gg, 256, smem_g128>>>(nullptr, 1, w_ih1, b_ih1, b_hh1);
    // layer-1 recurrence (writes g_h1last)
    k_rec<<<128, 256, smem_rec>>>(1);
    // FC head
    k_fc<<<BATCH, 64>>>(fc1_w, fc1_b, fc2_w, fc2_b, out);
}

// round 7
// speedup vs baseline: 1.2983x; 1.1117x over previous
#include <cuda_runtime.h>
#include <cuda_fp16.h>

#define BATCH  512
#define TSTEPS 256
#define IDIM   32
#define HDIM   128
#define GDIM   512                    // 4*H
#define MROWS  (BATCH * TSTEPS)       // 131072

typedef unsigned long long ull;

// ---------------- scratch (static device globals: allocation-free) ----------
__device__ __half g_xg[(size_t)MROWS * GDIM];   // 128 MB fp16, reused xg0/xg1
__device__ __half g_h0[(size_t)MROWS * HDIM];   // 32 MB fp16, layer-0 hidden
__device__ float  g_h1last[BATCH * HDIM];       // last hidden of layer 1
__device__ __half g_whh[2 * GDIM * HDIM];       // fp16 copies of w_hh0, w_hh1

// ---------------- f32x2 helpers (FFMA2 — PTX-only on sm_103a) ---------------
__device__ __forceinline__ ull pack2(float x, float y) {
    ull r; asm("mov.b64 %0, {%1, %2};" : "=l"(r) : "f"(x), "f"(y)); return r;
}
__device__ __forceinline__ void unpack2(ull v, float &x, float &y) {
    asm("mov.b64 {%0, %1}, %2;" : "=f"(x), "=f"(y) : "l"(v));
}
__device__ __forceinline__ void ffma2(ull &d, ull a, ull b) {
    asm("fma.rn.f32x2 %0, %1, %2, %0;" : "+l"(d) : "l"(a), "l"(b));
}

// ---------------- fast transcendentals ---------------------------------------
__device__ __forceinline__ float ex2f(float x) {
    float y; asm("ex2.approx.f32 %0, %1;" : "=f"(y) : "f"(x)); return y;
}
__device__ __forceinline__ float rcpf(float x) {
    float y; asm("rcp.approx.f32 %0, %1;" : "=f"(y) : "f"(x)); return y;
}
__device__ __forceinline__ float sigmf(float x) {
    return rcpf(1.0f + ex2f(-1.4426950408889634f * x));
}
__device__ __forceinline__ float tanhf_(float x) {
    return 2.0f * sigmf(2.0f * x) - 1.0f;
}

// ---------------- K0: convert recurrent weights to fp16 ---------------------
__global__ void k_convert(const float* __restrict__ w0, const float* __restrict__ w1) {
    int i = blockIdx.x * blockDim.x + threadIdx.x;
    if (i < GDIM * HDIM) {
        g_whh[i]               = __float2half(w0[i]);
        g_whh[GDIM * HDIM + i] = __float2half(w1[i]);
    }
}

// ---------------- K1/K3: xg[M,512] = A[M,K] @ W[512,K]^T + b1 + b2 (fp16 out)
// One CTA owns a 128-row strip and ALL 512 output cols (4 N-blocks looped,
// A tile loaded once). Thread = 8 rows x 8 cols per N-block via f32x2.
// useH0: A = g_h0 (fp16, resolved INSIDE the kernel — device symbol).
template<int K, bool USEH0>
__global__ __launch_bounds__(256) void k_gemm(const float* __restrict__ Aext,
                                              const float* __restrict__ W,
                                              const float* __restrict__ b1,
                                              const float* __restrict__ b2) {
    extern __shared__ float sm[];
    float* aT = sm;               // [K][132]  transposed A tile
    float* bT = sm + K * 132;     // [K][132]  transposed W block
    int t = threadIdx.x;

    // ---- load A tile once ----
    if (USEH0) {
        const __half* Ab = g_h0 + (size_t)blockIdx.x * 128 * K;
        #pragma unroll 4
        for (int i = t; i < 128 * K; i += 256) { int m = i / K, k = i % K; aT[k * 132 + m] = __half2float(Ab[i]); }
    } else {
        const float* Ab = Aext + (size_t)blockIdx.x * 128 * K;
        #pragma unroll 4
        for (int i = t; i < 128 * K; i += 256) { int m = i / K, k = i % K; aT[k * 132 + m] = Ab[i]; }
    }
    // ---- load first W block ----
    {
        const float* Wb = W;
        #pragma unroll 4
        for (int i = t; i < 128 * K; i += 256) { int n = i / K, k = i % K; bT[k * 132 + n] = Wb[i]; }
    }
    __syncthreads();

    int tx = t & 15, ty = t >> 4;
    int m0 = ty * 8, n0 = tx * 8;

    #pragma unroll 1
    for (int nb = 0; nb < 4; nb++) {
        ull acc[8][4];
        #pragma unroll
        for (int r = 0; r < 8; r++)
            #pragma unroll
            for (int p = 0; p < 4; p++) acc[r][p] = 0ULL;

        #pragma unroll 4
        for (int k = 0; k < K; k++) {
            float4 aA = *(const float4*)&aT[k * 132 + m0];
            float4 aB = *(const float4*)&aT[k * 132 + m0 + 4];
            float4 bA = *(const float4*)&bT[k * 132 + n0];
            float4 bB = *(const float4*)&bT[k * 132 + n0 + 4];
            ull bp[4] = { pack2(bA.x, bA.y), pack2(bA.z, bA.w), pack2(bB.x, bB.y), pack2(bB.z, bB.w) };
            float ael[8] = { aA.x, aA.y, aA.z, aA.w, aB.x, aB.y, aB.z, aB.w };
            #pragma unroll
            for (int r = 0; r < 8; r++) {
                ull ar = pack2(ael[r], ael[r]);
                ffma2(acc[r][0], ar, bp[0]);
                ffma2(acc[r][1], ar, bp[1]);
                ffma2(acc[r][2], ar, bp[2]);
                ffma2(acc[r][3], ar, bp[3]);
            }
        }

        // ---- epilogue: bias + convert to fp16, store 8 halfs per row ----
        int gc = nb * 128 + n0;
        float bias[8];
        #pragma unroll
        for (int j = 0; j < 8; j++) bias[j] = b1[gc + j] + b2[gc + j];
        size_t rowBase = ((size_t)blockIdx.x * 128 + m0) * GDIM + gc;
        #pragma unroll
        for (int r = 0; r < 8; r++) {
            float o[8];
            unpack2(acc[r][0], o[0], o[1]); unpack2(acc[r][1], o[2], o[3]);
            unpack2(acc[r][2], o[4], o[5]); unpack2(acc[r][3], o[6], o[7]);
            #pragma unroll
            for (int j = 0; j < 8; j++) o[j] += bias[j];
            __half2 p0 = __floats2half2_rn(o[0], o[1]);
            __half2 p1 = __floats2half2_rn(o[2], o[3]);
            __half2 p2 = __floats2half2_rn(o[4], o[5]);
            __half2 p3 = __floats2half2_rn(o[6], o[7]);
            uint4 pk;
            pk.x = *(unsigned*)&p0; pk.y = *(unsigned*)&p1;
            pk.z = *(unsigned*)&p2; pk.w = *(unsigned*)&p3;
            *(uint4*)&g_xg[rowBase + (size_t)r * GDIM] = pk;
        }

        __syncthreads();                      // everyone done reading bT
        if (nb < 3) {                         // load next W block
            const float* Wb = W + (size_t)(nb + 1) * 128 * K;
            #pragma unroll 4
            for (int i = t; i < 128 * K; i += 256) { int n = i / K, k = i % K; bT[k * 132 + n] = Wb[i]; }
            __syncthreads();
        }
    }
}

// ---------------- K2/K4: persistent LSTM recurrence -------------------------
// 128 CTAs x 256 threads; CTA owns 4 batch elems for all 256 steps.
// Split-K: thread (half=t>>7, tl=t&127) computes rows tl*4..+3, k in
// [half*64, +64). h stored DUPLICATED ((h,h) pairs) in SMEM for movless FFMA2.
// xg loads software-pipelined one step ahead (fp16).
__global__ __launch_bounds__(256) void k_rec(int layer) {
    extern __shared__ char smraw[];
    __half* wT   = (__half*)smraw;                        // [k][row] fp16, 128 KB
    float*  part = (float*)(smraw + 131072);              // [2][4][512] partials
    float*  hdup = (float*)(smraw + 131072 + 16384);      // [128][12]

    int t = threadIdx.x;
    const __half* wsrc = g_whh + layer * (GDIM * HDIM);
    for (int i = t; i < GDIM * HDIM; i += 256) {          // transpose load W_hh
        int r = i >> 7, k = i & 127;
        wT[k * GDIM + r] = wsrc[i];
    }
    for (int i = t; i < 128 * 12; i += 256) hdup[i] = 0.f;
    __syncthreads();

    const int half = t >> 7, tl = t & 127;
    const int r0 = tl * 4, kb = half * 64;
    const int b_lo = half, u = tl;                        // elementwise role
    float cst[2] = {0.f, 0.f};
    const size_t cta_b = (size_t)blockIdx.x * 4;
    const __half* xgb = g_xg + (cta_b << 17);             // cta_b * TSTEPS * GDIM
    float* p_my = part + half * 2048;

    const __half* xbase0 = xgb + ((size_t)b_lo << 17) + u;
    const __half* xbase1 = xbase0 + ((size_t)2 << 17);

    __half xc[8];
    {   // prime the pipeline: step 0 xg
        const __half* xp0 = xbase0;
        const __half* xp1 = xbase1;
        xc[0] = xp0[0]; xc[1] = xp0[128]; xc[2] = xp0[256]; xc[3] = xp0[384];
        xc[4] = xp1[0]; xc[5] = xp1[128]; xc[6] = xp1[256]; xc[7] = xp1[384];
    }

    for (int ts = 0; ts < TSTEPS; ts++) {
        // ---- prefetch next step's xg (hidden under this step's matmul) ----
        __half xn[8];
        if (ts < TSTEPS - 1) {
            const __half* xp0 = xbase0 + (size_t)(ts + 1) * GDIM;
            const __half* xp1 = xbase1 + (size_t)(ts + 1) * GDIM;
            xn[0] = xp0[0]; xn[1] = xp0[128]; xn[2] = xp0[256]; xn[3] = xp0[384];
            xn[4] = xp1[0]; xn[5] = xp1[128]; xn[6] = xp1[256]; xn[7] = xp1[384];
        }

        // ---- partial gates = h @ W_hh^T (rows r0..r0+3, batches 0..3) ------
        ull acc[4][2];
        #pragma unroll
        for (int b = 0; b < 4; b++) { acc[b][0] = 0ULL; acc[b][1] = 0ULL; }

        #pragma unroll 8
        for (int kk = 0; kk < 64; kk++) {
            int k = kb + kk;
            uint2 wr = *(const uint2*)&wT[k * GDIM + r0];           // 4 fp16 weights
            float2 f01 = __half22float2(*(__half2*)&wr.x);          // rows r0, r0+1
            float2 f23 = __half22float2(*(__half2*)&wr.y);          // rows r0+2, r0+3
            ull w01 = pack2(f01.x, f01.y);
            ull w23 = pack2(f23.x, f23.y);
            const float4* hp = (const float4*)(hdup + k * 12);
            float4 h0v = hp[0], h1v = hp[1];                        // (b0,b0,b1,b1),(b2,b2,b3,b3)
            ull hb0 = pack2(h0v.x, h0v.y), hb1 = pack2(h0v.z, h0v.w);
            ull hb2 = pack2(h1v.x, h1v.y), hb3 = pack2(h1v.z, h1v.w);
            ffma2(acc[0][0], w01, hb0); ffma2(acc[0][1], w23, hb0);
            ffma2(acc[1][0], w01, hb1); ffma2(acc[1][1], w23, hb1);
            ffma2(acc[2][0], w01, hb2); ffma2(acc[2][1], w23, hb2);
            ffma2(acc[3][0], w01, hb3); ffma2(acc[3][1], w23, hb3);
        }
        #pragma unroll
        for (int b = 0; b < 4; b++) {
            float lo, hi;
            unpack2(acc[b][0], lo, hi); *(float2*)&p_my[b * 512 + r0]     = make_float2(lo, hi);
            unpack2(acc[b][1], lo, hi); *(float2*)&p_my[b * 512 + r0 + 2] = make_float2(lo, hi);
        }
        __syncthreads();

        // ---- elementwise LSTM cell: cells (b_lo,u) and (b_lo+2,u) ----------
        #pragma unroll
        for (int j = 0; j < 2; j++) {
            int b = b_lo + 2 * j;
            const float* pa = &part[b * 512];
            const float* pb = &part[2048 + b * 512];
            float gi = sigmf (pa[u]       + pb[u]       + __half2float(xc[4*j + 0]));
            float gf = sigmf (pa[u + 128] + pb[u + 128] + __half2float(xc[4*j + 1]));
            float gg = tanhf_(pa[u + 256] + pb[u + 256] + __half2float(xc[4*j + 2]));
            float go = sigmf (pa[u + 384] + pb[u + 384] + __half2float(xc[4*j + 3]));
            cst[j] = gf * cst[j] + gi * gg;
            float h = go * tanhf_(cst[j]);
            *(float2*)&hdup[u * 12 + 2 * b] = make_float2(h, h);
            if (layer == 0)
                g_h0[((cta_b + b) * TSTEPS + ts) * HDIM + u] = __float2half(h);
            else if (ts == TSTEPS - 1)
                g_h1last[(cta_b + b) * HDIM + u] = h;
        }
        __syncthreads();

        #pragma unroll
        for (int i = 0; i < 8; i++) xc[i] = xn[i];
    }
}

// ---------------- K5: FC head  out = relu(h @ fc1^T + b1) @ fc2^T + b2 ------
__global__ void k_fc(const float* __restrict__ w1, const float* __restrict__ b1,
                     const float* __restrict__ w2, const float* __restrict__ b2,
                     float* __restrict__ out) {
    __shared__ float red[2];
    int b = blockIdx.x, j = threadIdx.x;   // 64 threads
    const float* hv = g_h1last + b * HDIM;
    const float* wr = w1 + j * HDIM;
    float acc = b1[j];
    #pragma unroll 4
    for (int k = 0; k < HDIM; k++) acc += hv[k] * wr[k];
    float z = fmaxf(acc, 0.0f) * w2[j];
    #pragma unroll
    for (int off = 16; off > 0; off >>= 1) z += __shfl_down_sync(0xffffffffu, z, off);
    if ((j & 31) == 0) red[j >> 5] = z;
    __syncthreads();
    if (j == 0) out[b] = red[0] + red[1] + b2[0];
}

// ---------------- launch -----------------------------------------------------
extern "C" void kernel_launch(void* const* d_in, const int* in_sizes, int n_in,
                              void* d_out, int out_size) {
    const float* x     = (const float*)d_in[0];
    const float* w_ih0 = (const float*)d_in[1];
    const float* w_hh0 = (const float*)d_in[2];
    const float* b_ih0 = (const float*)d_in[3];
    const float* b_hh0 = (const float*)d_in[4];
    const float* w_ih1 = (const float*)d_in[5];
    const float* w_hh1 = (const float*)d_in[6];
    const float* b_ih1 = (const float*)d_in[7];
    const float* b_hh1 = (const float*)d_in[8];
    const float* fc1_w = (const float*)d_in[9];
    const float* fc1_b = (const float*)d_in[10];
    const float* fc2_w = (const float*)d_in[11];
    const float* fc2_b = (const float*)d_in[12];
    float* out = (float*)d_out;

    const int smem_g128 = 2 * 128 * 132 * 4;              // 135168
    const int smem_g32  = 2 * 32 * 132 * 4;               // 33792
    const int smem_rec  = 131072 + 16384 + 128 * 12 * 4;  // 153600
    cudaFuncSetAttribute(k_gemm<128, true>,  cudaFuncAttributeMaxDynamicSharedMemorySize, smem_g128);
    cudaFuncSetAttribute(k_gemm<32, false>,  cudaFuncAttributeMaxDynamicSharedMemorySize, smem_g32);
    cudaFuncSetAttribute(k_rec,              cudaFuncAttributeMaxDynamicSharedMemorySize, smem_rec);

    k_convert<<<(GDIM * HDIM + 255) / 256, 256>>>(w_hh0, w_hh1);

    // xg0 = x @ w_ih0^T + b_ih0 + b_hh0           (K = 32, A = external fp32 x)
    k_gemm<32, false><<<MROWS / 128, 256, smem_g32>>>(x, w_ih0, b_ih0, b_hh0);
    // layer-0 recurrence (writes g_h0 fp16)
    k_rec<<<128, 256, smem_rec>>>(0);
    // xg1 = h0 @ w_ih1^T + b_ih1 + b_hh1          (K = 128, A = g_h0 fp16, in-kernel)
    k_gemm<128, true><<<MROWS / 128, 256, smem_g128>>>(nullptr, w_ih1, b_ih1, b_hh1);
    // layer-1 recurrence (writes g_h1last)
    k_rec<<<128, 256, smem_rec>>>(1);
    // FC head
    k_fc<<<BATCH, 64>>>(fc1_w, fc1_b, fc2_w, fc2_b, out);
}

// round 8
// speedup vs baseline: 2.5928x; 1.9971x over previous
#include <cuda_runtime.h>
#include <cuda_fp16.h>

#define BATCH  512
#define TSTEPS 256
#define IDIM   32
#define HDIM   128
#define GDIM   512                    // 4*H
#define MROWS  (BATCH * TSTEPS)       // 131072

typedef unsigned long long ull;

// ---------------- scratch (static device globals: allocation-free) ----------
__device__ __half g_xg[(size_t)MROWS * GDIM];   // 128 MB fp16, reused xg0/xg1
__device__ __half g_h0[(size_t)MROWS * HDIM];   // 32 MB fp16, layer-0 hidden
__device__ float  g_h1last[BATCH * HDIM];       // last hidden of layer 1
__device__ __half g_whh[2 * GDIM * HDIM];       // fp16 copies of w_hh0, w_hh1

// ---------------- f32x2 helpers (FFMA2 — PTX-only on sm_103a) ---------------
__device__ __forceinline__ ull pack2(float x, float y) {
    ull r; asm("mov.b64 %0, {%1, %2};" : "=l"(r) : "f"(x), "f"(y)); return r;
}
__device__ __forceinline__ void unpack2(ull v, float &x, float &y) {
    asm("mov.b64 {%0, %1}, %2;" : "=f"(x), "=f"(y) : "l"(v));
}
__device__ __forceinline__ void ffma2(ull &d, ull a, ull b) {
    asm("fma.rn.f32x2 %0, %1, %2, %0;" : "+l"(d) : "l"(a), "l"(b));
}

// ---------------- fast transcendentals ---------------------------------------
__device__ __forceinline__ float ex2f(float x) {
    float y; asm("ex2.approx.f32 %0, %1;" : "=f"(y) : "f"(x)); return y;
}
__device__ __forceinline__ float rcpf(float x) {
    float y; asm("rcp.approx.f32 %0, %1;" : "=f"(y) : "f"(x)); return y;
}
__device__ __forceinline__ float sigmf(float x) {
    return rcpf(1.0f + ex2f(-1.4426950408889634f * x));
}
__device__ __forceinline__ float tanhf_(float x) {
    return 2.0f * sigmf(2.0f * x) - 1.0f;
}

// ---------------- HMMA m16n8k16 fp16->fp32 -----------------------------------
__device__ __forceinline__ void hmma(float* c, const unsigned* a, unsigned b0, unsigned b1) {
    asm volatile("mma.sync.aligned.m16n8k16.row.col.f32.f16.f16.f32 "
        "{%0,%1,%2,%3}, {%4,%5,%6,%7}, {%8,%9}, {%0,%1,%2,%3};"
        : "+f"(c[0]), "+f"(c[1]), "+f"(c[2]), "+f"(c[3])
        : "r"(a[0]), "r"(a[1]), "r"(a[2]), "r"(a[3]), "r"(b0), "r"(b1));
}

// ---------------- K0: convert recurrent weights to fp16 ---------------------
__global__ void k_convert(const float* __restrict__ w0, const float* __restrict__ w1) {
    int i = blockIdx.x * blockDim.x + threadIdx.x;
    if (i < GDIM * HDIM) {
        g_whh[i]               = __float2half(w0[i]);
        g_whh[GDIM * HDIM + i] = __float2half(w1[i]);
    }
}

// ---------------- K1/K3: xg[M,512] = A[M,K] @ W[512,K]^T + b1 + b2 (fp16 out)
// (unchanged from R7 — FFMA2 path; HMMA port is next round's change)
template<int K, bool USEH0>
__global__ __launch_bounds__(256) void k_gemm(const float* __restrict__ Aext,
                                              const float* __restrict__ W,
                                              const float* __restrict__ b1,
                                              const float* __restrict__ b2) {
    extern __shared__ float sm[];
    float* aT = sm;               // [K][132]  transposed A tile
    float* bT = sm + K * 132;     // [K][132]  transposed W block
    int t = threadIdx.x;

    if (USEH0) {
        const __half* Ab = g_h0 + (size_t)blockIdx.x * 128 * K;
        #pragma unroll 4
        for (int i = t; i < 128 * K; i += 256) { int m = i / K, k = i % K; aT[k * 132 + m] = __half2float(Ab[i]); }
    } else {
        const float* Ab = Aext + (size_t)blockIdx.x * 128 * K;
        #pragma unroll 4
        for (int i = t; i < 128 * K; i += 256) { int m = i / K, k = i % K; aT[k * 132 + m] = Ab[i]; }
    }
    {
        const float* Wb = W;
        #pragma unroll 4
        for (int i = t; i < 128 * K; i += 256) { int n = i / K, k = i % K; bT[k * 132 + n] = Wb[i]; }
    }
    __syncthreads();

    int tx = t & 15, ty = t >> 4;
    int m0 = ty * 8, n0 = tx * 8;

    #pragma unroll 1
    for (int nb = 0; nb < 4; nb++) {
        ull acc[8][4];
        #pragma unroll
        for (int r = 0; r < 8; r++)
            #pragma unroll
            for (int p = 0; p < 4; p++) acc[r][p] = 0ULL;

        #pragma unroll 4
        for (int k = 0; k < K; k++) {
            float4 aA = *(const float4*)&aT[k * 132 + m0];
            float4 aB = *(const float4*)&aT[k * 132 + m0 + 4];
            float4 bA = *(const float4*)&bT[k * 132 + n0];
            float4 bB = *(const float4*)&bT[k * 132 + n0 + 4];
            ull bp[4] = { pack2(bA.x, bA.y), pack2(bA.z, bA.w), pack2(bB.x, bB.y), pack2(bB.z, bB.w) };
            float ael[8] = { aA.x, aA.y, aA.z, aA.w, aB.x, aB.y, aB.z, aB.w };
            #pragma unroll
            for (int r = 0; r < 8; r++) {
                ull ar = pack2(ael[r], ael[r]);
                ffma2(acc[r][0], ar, bp[0]);
                ffma2(acc[r][1], ar, bp[1]);
                ffma2(acc[r][2], ar, bp[2]);
                ffma2(acc[r][3], ar, bp[3]);
            }
        }

        int gc = nb * 128 + n0;
        float bias[8];
        #pragma unroll
        for (int j = 0; j < 8; j++) bias[j] = b1[gc + j] + b2[gc + j];
        size_t rowBase = ((size_t)blockIdx.x * 128 + m0) * GDIM + gc;
        #pragma unroll
        for (int r = 0; r < 8; r++) {
            float o[8];
            unpack2(acc[r][0], o[0], o[1]); unpack2(acc[r][1], o[2], o[3]);
            unpack2(acc[r][2], o[4], o[5]); unpack2(acc[r][3], o[6], o[7]);
            #pragma unroll
            for (int j = 0; j < 8; j++) o[j] += bias[j];
            __half2 p0 = __floats2half2_rn(o[0], o[1]);
            __half2 p1 = __floats2half2_rn(o[2], o[3]);
            __half2 p2 = __floats2half2_rn(o[4], o[5]);
            __half2 p3 = __floats2half2_rn(o[6], o[7]);
            uint4 pk;
            pk.x = *(unsigned*)&p0; pk.y = *(unsigned*)&p1;
            pk.z = *(unsigned*)&p2; pk.w = *(unsigned*)&p3;
            *(uint4*)&g_xg[rowBase + (size_t)r * GDIM] = pk;
        }

        __syncthreads();
        if (nb < 3) {
            const float* Wb = W + (size_t)(nb + 1) * 128 * K;
            #pragma unroll 4
            for (int i = t; i < 128 * K; i += 256) { int n = i / K, k = i % K; bT[k * 132 + n] = Wb[i]; }
            __syncthreads();
        }
    }
}

// ---------------- K2/K4: persistent LSTM recurrence via HMMA -----------------
// 128 CTAs x 512 threads (16 warps); CTA owns 4 batch elems for all 256 steps.
// gates[512,8] = W_hh[512,128] @ hT[128,8]^T per step:
//   warp w owns gate rows 32w..32w+31 (2 m16 tiles); W A-fragments preloaded
//   into registers ONCE (loop-invariant). B frags = LDS.32 pairs from
//   hT[batch][k] fp16 (pad 136 -> conflict-free). Elementwise: 1 cell/thread.
#define GPITCH 10
__global__ __launch_bounds__(512, 1) void k_rec(int layer) {
    __shared__ float  gates[GDIM * GPITCH];     // 20480 B, [row][col(batch)] pitch 10
    __shared__ __half hT[8 * 136];              // [batch][k] fp16, pad 136

    const int t    = threadIdx.x;
    const int warp = t >> 5, lane = t & 31;
    const int g    = lane >> 2, tg = lane & 3;

    // ---- preload W_hh A-fragments (2 m-tiles x 8 k-tiles x 4 regs) ----------
    const __half* Wg = g_whh + layer * (GDIM * HDIM);
    unsigned afr[2][8][4];
    #pragma unroll
    for (int mt = 0; mt < 2; mt++) {
        int rbase = warp * 32 + mt * 16;
        #pragma unroll
        for (int kt = 0; kt < 8; kt++) {
            int kb = kt * 16 + tg * 2;
            afr[mt][kt][0] = *(const unsigned*)&Wg[(rbase + g)     * HDIM + kb];
            afr[mt][kt][1] = *(const unsigned*)&Wg[(rbase + g + 8) * HDIM + kb];
            afr[mt][kt][2] = *(const unsigned*)&Wg[(rbase + g)     * HDIM + kb + 8];
            afr[mt][kt][3] = *(const unsigned*)&Wg[(rbase + g + 8) * HDIM + kb + 8];
        }
    }

    for (int i = t; i < 8 * 136; i += 512) hT[i] = __float2half(0.f);

    // ---- elementwise role: one cell (b, u) per thread ----------------------
    const int b = t >> 7;            // 0..3
    const int u = t & 127;
    float cstate = 0.f;
    const size_t cta_b = (size_t)blockIdx.x * 4;
    const __half* xbase = g_xg + (cta_b + b) * ((size_t)TSTEPS * GDIM) + u;

    __half xc[4];
    xc[0] = xbase[0]; xc[1] = xbase[128]; xc[2] = xbase[256]; xc[3] = xbase[384];
    __syncthreads();

    for (int ts = 0; ts < TSTEPS; ts++) {
        // prefetch next step's xg (hidden under this step's matmul)
        __half xn[4];
        if (ts < TSTEPS - 1) {
            const __half* xp = xbase + (size_t)(ts + 1) * GDIM;
            xn[0] = xp[0]; xn[1] = xp[128]; xn[2] = xp[256]; xn[3] = xp[384];
        }

        // ---- tensor-core matmul: gates_pre = W_hh @ h ----------------------
        float acc[2][4];
        #pragma unroll
        for (int mt = 0; mt < 2; mt++)
            #pragma unroll
            for (int p = 0; p < 4; p++) acc[mt][p] = 0.f;

        #pragma unroll
        for (int kt = 0; kt < 8; kt++) {
            unsigned b0 = *(const unsigned*)&hT[g * 136 + kt * 16 + tg * 2];
            unsigned b1 = *(const unsigned*)&hT[g * 136 + kt * 16 + tg * 2 + 8];
            hmma(acc[0], afr[0][kt], b0, b1);
            hmma(acc[1], afr[1][kt], b0, b1);
        }
        #pragma unroll
        for (int mt = 0; mt < 2; mt++) {
            int r = warp * 32 + mt * 16 + g;
            *(float2*)&gates[r * GPITCH + 2 * tg]       = make_float2(acc[mt][0], acc[mt][1]);
            *(float2*)&gates[(r + 8) * GPITCH + 2 * tg] = make_float2(acc[mt][2], acc[mt][3]);
        }
        __syncthreads();

        // ---- elementwise LSTM cell -----------------------------------------
        {
            int base = u * GPITCH + b;
            float gi = sigmf (gates[base]                + __half2float(xc[0]));
            float gf = sigmf (gates[base + 128 * GPITCH] + __half2float(xc[1]));
            float gg = tanhf_(gates[base + 256 * GPITCH] + __half2float(xc[2]));
            float go = sigmf (gates[base + 384 * GPITCH] + __half2float(xc[3]));
            cstate = gf * cstate + gi * gg;
            float h = go * tanhf_(cstate);
            hT[b * 136 + u] = __float2half(h);
            if (layer == 0)
                g_h0[((cta_b + b) * TSTEPS + ts) * HDIM + u] = __float2half(h);
            else if (ts == TSTEPS - 1)
                g_h1last[(cta_b + b) * HDIM + u] = h;
        }
        __syncthreads();

        xc[0] = xn[0]; xc[1] = xn[1]; xc[2] = xn[2]; xc[3] = xn[3];
    }
}

// ---------------- K5: FC head  out = relu(h @ fc1^T + b1) @ fc2^T + b2 ------
__global__ void k_fc(const float* __restrict__ w1, const float* __restrict__ b1,
                     const float* __restrict__ w2, const float* __restrict__ b2,
                     float* __restrict__ out) {
    __shared__ float red[2];
    int b = blockIdx.x, j = threadIdx.x;   // 64 threads
    const float* hv = g_h1last + b * HDIM;
    const float* wr = w1 + j * HDIM;
    float acc = b1[j];
    #pragma unroll 4
    for (int k = 0; k < HDIM; k++) acc += hv[k] * wr[k];
    float z = fmaxf(acc, 0.0f) * w2[j];
    #pragma unroll
    for (int off = 16; off > 0; off >>= 1) z += __shfl_down_sync(0xffffffffu, z, off);
    if ((j & 31) == 0) red[j >> 5] = z;
    __syncthreads();
    if (j == 0) out[b] = red[0] + red[1] + b2[0];
}

// ---------------- launch -----------------------------------------------------
extern "C" void kernel_launch(void* const* d_in, const int* in_sizes, int n_in,
                              void* d_out, int out_size) {
    const float* x     = (const float*)d_in[0];
    const float* w_ih0 = (const float*)d_in[1];
    const float* w_hh0 = (const float*)d_in[2];
    const float* b_ih0 = (const float*)d_in[3];
    const float* b_hh0 = (const float*)d_in[4];
    const float* w_ih1 = (const float*)d_in[5];
    const float* w_hh1 = (const float*)d_in[6];
    const float* b_ih1 = (const float*)d_in[7];
    const float* b_hh1 = (const float*)d_in[8];
    const float* fc1_w = (const float*)d_in[9];
    const float* fc1_b = (const float*)d_in[10];
    const float* fc2_w = (const float*)d_in[11];
    const float* fc2_b = (const float*)d_in[12];
    float* out = (float*)d_out;

    const int smem_g128 = 2 * 128 * 132 * 4;              // 135168
    const int smem_g32  = 2 * 32 * 132 * 4;               // 33792
    cudaFuncSetAttribute(k_gemm<128, true>,  cudaFuncAttributeMaxDynamicSharedMemorySize, smem_g128);
    cudaFuncSetAttribute(k_gemm<32, false>,  cudaFuncAttributeMaxDynamicSharedMemorySize, smem_g32);

    k_convert<<<(GDIM * HDIM + 255) / 256, 256>>>(w_hh0, w_hh1);

    // xg0 = x @ w_ih0^T + b_ih0 + b_hh0           (K = 32, A = external fp32 x)
    k_gemm<32, false><<<MROWS / 128, 256, smem_g32>>>(x, w_ih0, b_ih0, b_hh0);
    // layer-0 recurrence (HMMA, writes g_h0 fp16)
    k_rec<<<128, 512>>>(0);
    // xg1 = h0 @ w_ih1^T + b_ih1 + b_hh1          (K = 128, A = g_h0 fp16)
    k_gemm<128, true><<<MROWS / 128, 256, smem_g128>>>(nullptr, w_ih1, b_ih1, b_hh1);
    // layer-1 recurrence (HMMA, writes g_h1last)
    k_rec<<<128, 512>>>(1);
    // FC head
    k_fc<<<BATCH, 64>>>(fc1_w, fc1_b, fc2_w, fc2_b, out);
}

// round 9
// speedup vs baseline: 5.0115x; 1.9328x over previous
#include <cuda_runtime.h>
#include <cuda_fp16.h>

#define BATCH  512
#define TSTEPS 256
#define IDIM   32
#define HDIM   128
#define GDIM   512                    // 4*H
#define MROWS  (BATCH * TSTEPS)       // 131072
#define GPITCH 10

typedef unsigned long long ull;

// ---------------- scratch (static device globals: allocation-free) ----------
__device__ __half g_xg[(size_t)MROWS * GDIM];   // 128 MB fp16, xg1 only
__device__ __half g_h0[(size_t)MROWS * HDIM];   // 32 MB fp16, layer-0 hidden
__device__ float  g_h1last[BATCH * HDIM];       // last hidden of layer 1
__device__ __half g_whh[2 * GDIM * HDIM];       // fp16 w_hh0, w_hh1
__device__ __half g_wih0[GDIM * IDIM];          // fp16 w_ih0
__device__ __half g_wih1[GDIM * HDIM];          // fp16 w_ih1
__device__ __half g_xh[(size_t)BATCH * TSTEPS * IDIM];  // fp16 x
__device__ float  g_bsum0[GDIM], g_bsum1[GDIM]; // b_ih + b_hh

// ---------------- fast transcendentals ---------------------------------------
__device__ __forceinline__ float ex2f(float x) {
    float y; asm("ex2.approx.f32 %0, %1;" : "=f"(y) : "f"(x)); return y;
}
__device__ __forceinline__ float rcpf(float x) {
    float y; asm("rcp.approx.f32 %0, %1;" : "=f"(y) : "f"(x)); return y;
}
__device__ __forceinline__ float sigmf(float x) {
    return rcpf(1.0f + ex2f(-1.4426950408889634f * x));
}
__device__ __forceinline__ float tanhf_(float x) {
    return 2.0f * sigmf(2.0f * x) - 1.0f;
}

// ---------------- HMMA m16n8k16 fp16->fp32 -----------------------------------
__device__ __forceinline__ void hmma(float* c, const unsigned* a, unsigned b0, unsigned b1) {
    asm volatile("mma.sync.aligned.m16n8k16.row.col.f32.f16.f16.f32 "
        "{%0,%1,%2,%3}, {%4,%5,%6,%7}, {%8,%9}, {%0,%1,%2,%3};"
        : "+f"(c[0]), "+f"(c[1]), "+f"(c[2]), "+f"(c[3])
        : "r"(a[0]), "r"(a[1]), "r"(a[2]), "r"(a[3]), "r"(b0), "r"(b1));
}

// ---------------- K0: fp16 conversions + bias sums ---------------------------
__global__ void k_convert(const float* __restrict__ x,
                          const float* __restrict__ w_ih0, const float* __restrict__ w_hh0,
                          const float* __restrict__ b_ih0, const float* __restrict__ b_hh0,
                          const float* __restrict__ w_ih1, const float* __restrict__ w_hh1,
                          const float* __restrict__ b_ih1, const float* __restrict__ b_hh1) {
    int i = blockIdx.x * blockDim.x + threadIdx.x;
    if (i < BATCH * TSTEPS * IDIM) g_xh[i] = __float2half(x[i]);
    if (i < GDIM * HDIM) {
        g_whh[i]               = __float2half(w_hh0[i]);
        g_whh[GDIM * HDIM + i] = __float2half(w_hh1[i]);
        g_wih1[i]              = __float2half(w_ih1[i]);
    }
    if (i < GDIM * IDIM) g_wih0[i] = __float2half(w_ih0[i]);
    if (i < GDIM) {
        g_bsum0[i] = b_ih0[i] + b_hh0[i];
        g_bsum1[i] = b_ih1[i] + b_hh1[i];
    }
}

// ---------------- K1: layer-0 fused (input GEMM + recurrence), HMMA ----------
// 128 CTAs x 512 threads; CTA owns 4 batch elems, x tile resident in smem.
// Per step, per warp: 4 HMMA (x-part, K=32) + 16 HMMA (h-part, K=128).
__global__ __launch_bounds__(512, 1) void k_rec0() {
    extern __shared__ char smr[];
    __half* xtile = (__half*)smr;                   // [ts][8][40] fp16, 163840 B
    float*  gates = (float*)(smr + 163840);         // [row][GPITCH] f32, 20480 B
    __half* hT    = (__half*)(smr + 184320);        // [8][136] fp16, 2176 B

    const int t = threadIdx.x;
    const int warp = t >> 5, lane = t & 31;
    const int g = lane >> 2, tg = lane & 3;
    const size_t cta_b = (size_t)blockIdx.x * 4;

    // ---- preload weight fragments (loop-invariant) ----
    unsigned ah[2][8][4], ax[2][2][4];
    #pragma unroll
    for (int mt = 0; mt < 2; mt++) {
        int rbase = warp * 32 + mt * 16;
        #pragma unroll
        for (int kt = 0; kt < 8; kt++) {
            int kb = kt * 16 + tg * 2;
            ah[mt][kt][0] = *(const unsigned*)&g_whh[(rbase + g)     * HDIM + kb];
            ah[mt][kt][1] = *(const unsigned*)&g_whh[(rbase + g + 8) * HDIM + kb];
            ah[mt][kt][2] = *(const unsigned*)&g_whh[(rbase + g)     * HDIM + kb + 8];
            ah[mt][kt][3] = *(const unsigned*)&g_whh[(rbase + g + 8) * HDIM + kb + 8];
        }
        #pragma unroll
        for (int kt = 0; kt < 2; kt++) {
            int kb = kt * 16 + tg * 2;
            ax[mt][kt][0] = *(const unsigned*)&g_wih0[(rbase + g)     * IDIM + kb];
            ax[mt][kt][1] = *(const unsigned*)&g_wih0[(rbase + g + 8) * IDIM + kb];
            ax[mt][kt][2] = *(const unsigned*)&g_wih0[(rbase + g)     * IDIM + kb + 8];
            ax[mt][kt][3] = *(const unsigned*)&g_wih0[(rbase + g + 8) * IDIM + kb + 8];
        }
    }

    // ---- zero xtile + hT, then load x for batches 0..3 ----
    uint4 zz; zz.x = zz.y = zz.z = zz.w = 0u;
    uint4* xd = (uint4*)xtile;                      // row pitch = 5 uint4 (40 halves)
    for (int i = t; i < 256 * 8 * 5; i += 512) xd[i] = zz;
    for (int i = t; i < 8 * 136 / 8; i += 512) ((uint4*)hT)[i] = zz;
    __syncthreads();
    const uint4* xs = (const uint4*)g_xh;           // [b][ts][32] -> 4 uint4 per (b,ts)
    for (int i = t; i < 256 * 4 * 4; i += 512) {
        int ts = i >> 4, b = (i >> 2) & 3, q = i & 3;
        xd[(ts * 8 + b) * 5 + q] = xs[(cta_b + b) * 1024 + ts * 4 + q];
    }

    // ---- elementwise role: one cell (b, u) per thread ----
    const int eb = t >> 7, u = t & 127;
    const float bs_i = g_bsum0[u], bs_f = g_bsum0[u + 128];
    const float bs_g = g_bsum0[u + 256], bs_o = g_bsum0[u + 384];
    float cstate = 0.f;
    __syncthreads();

    for (int ts = 0; ts < TSTEPS; ts++) {
        float acc[2][4];
        #pragma unroll
        for (int mt = 0; mt < 2; mt++)
            #pragma unroll
            for (int p = 0; p < 4; p++) acc[mt][p] = 0.f;

        // x-part (K = 32)
        #pragma unroll
        for (int kt = 0; kt < 2; kt++) {
            unsigned b0 = *(const unsigned*)&xtile[(ts * 8 + g) * 40 + kt * 16 + tg * 2];
            unsigned b1 = *(const unsigned*)&xtile[(ts * 8 + g) * 40 + kt * 16 + tg * 2 + 8];
            hmma(acc[0], ax[0][kt], b0, b1);
            hmma(acc[1], ax[1][kt], b0, b1);
        }
        // h-part (K = 128)
        #pragma unroll
        for (int kt = 0; kt < 8; kt++) {
            unsigned b0 = *(const unsigned*)&hT[g * 136 + kt * 16 + tg * 2];
            unsigned b1 = *(const unsigned*)&hT[g * 136 + kt * 16 + tg * 2 + 8];
            hmma(acc[0], ah[0][kt], b0, b1);
            hmma(acc[1], ah[1][kt], b0, b1);
        }
        #pragma unroll
        for (int mt = 0; mt < 2; mt++) {
            int r = warp * 32 + mt * 16 + g;
            *(float2*)&gates[r * GPITCH + 2 * tg]       = make_float2(acc[mt][0], acc[mt][1]);
            *(float2*)&gates[(r + 8) * GPITCH + 2 * tg] = make_float2(acc[mt][2], acc[mt][3]);
        }
        __syncthreads();

        {
            int base = u * GPITCH + eb;
            float gi = sigmf (gates[base]                + bs_i);
            float gf = sigmf (gates[base + 128 * GPITCH] + bs_f);
            float gg = tanhf_(gates[base + 256 * GPITCH] + bs_g);
            float go = sigmf (gates[base + 384 * GPITCH] + bs_o);
            cstate = gf * cstate + gi * gg;
            float h = go * tanhf_(cstate);
            hT[eb * 136 + u] = __float2half(h);
            g_h0[((cta_b + eb) * TSTEPS + ts) * HDIM + u] = __float2half(h);
        }
        __syncthreads();
    }
}

// ---------------- K2: xg1[M,512] = h0[M,128] @ w_ih1^T + bsum1 (HMMA) --------
// 1024 CTAs x 512 threads; CTA owns 128 rows (16 chunks of 8). W fragments in
// registers (loaded once); A rows double-buffered in smem; epilogue transposed
// through smem for uint4 fp16 stores.
__global__ __launch_bounds__(512, 1) void k_gemmh() {
    __shared__ __half atile[2][8 * 136];            // 2 x 2176 B
    __shared__ __half gtile[8 * 520];               // 8320 B
    const int t = threadIdx.x;
    const int warp = t >> 5, lane = t & 31;
    const int g = lane >> 2, tg = lane & 3;
    const size_t row0 = (size_t)blockIdx.x * 128;

    unsigned afr[2][8][4];
    float bb[2][2];
    #pragma unroll
    for (int mt = 0; mt < 2; mt++) {
        int rbase = warp * 32 + mt * 16;
        #pragma unroll
        for (int kt = 0; kt < 8; kt++) {
            int kb = kt * 16 + tg * 2;
            afr[mt][kt][0] = *(const unsigned*)&g_wih1[(rbase + g)     * HDIM + kb];
            afr[mt][kt][1] = *(const unsigned*)&g_wih1[(rbase + g + 8) * HDIM + kb];
            afr[mt][kt][2] = *(const unsigned*)&g_wih1[(rbase + g)     * HDIM + kb + 8];
            afr[mt][kt][3] = *(const unsigned*)&g_wih1[(rbase + g + 8) * HDIM + kb + 8];
        }
        bb[mt][0] = g_bsum1[rbase + g];
        bb[mt][1] = g_bsum1[rbase + g + 8];
    }

    // load chunk 0
    if (t < 128) {
        int r = t >> 4, q = t & 15;
        *(uint4*)&atile[0][r * 136 + q * 8] = *(const uint4*)(g_h0 + (row0 + r) * HDIM + q * 8);
    }
    __syncthreads();

    #pragma unroll 1
    for (int c = 0; c < 16; c++) {
        int buf = c & 1;
        float acc[2][4];
        #pragma unroll
        for (int mt = 0; mt < 2; mt++)
            #pragma unroll
            for (int p = 0; p < 4; p++) acc[mt][p] = 0.f;

        #pragma unroll
        for (int kt = 0; kt < 8; kt++) {
            unsigned b0 = *(const unsigned*)&atile[buf][g * 136 + kt * 16 + tg * 2];
            unsigned b1 = *(const unsigned*)&atile[buf][g * 136 + kt * 16 + tg * 2 + 8];
            hmma(acc[0], afr[0][kt], b0, b1);
            hmma(acc[1], afr[1][kt], b0, b1);
        }

        // prefetch next chunk into the other buffer (safe: 2 syncs since its last use)
        if (c < 15 && t < 128) {
            int r = t >> 4, q = t & 15;
            *(uint4*)&atile[buf ^ 1][r * 136 + q * 8] =
                *(const uint4*)(g_h0 + (row0 + (c + 1) * 8 + r) * HDIM + q * 8);
        }

        // epilogue: transpose through smem (gtile[n][gate])
        #pragma unroll
        for (int mt = 0; mt < 2; mt++) {
            int r = warp * 32 + mt * 16 + g;
            gtile[(2 * tg)     * 520 + r]     = __float2half(acc[mt][0] + bb[mt][0]);
            gtile[(2 * tg + 1) * 520 + r]     = __float2half(acc[mt][1] + bb[mt][0]);
            gtile[(2 * tg)     * 520 + r + 8] = __float2half(acc[mt][2] + bb[mt][1]);
            gtile[(2 * tg + 1) * 520 + r + 8] = __float2half(acc[mt][3] + bb[mt][1]);
        }
        __syncthreads();

        {   // copy out: 8 rows x 512 halves = 512 uint4
            int n = t >> 6, off = (t & 63) * 8;
            uint4 v = *(uint4*)&gtile[n * 520 + off];
            *(uint4*)(g_xg + (row0 + c * 8 + n) * GDIM + off) = v;
        }
        __syncthreads();
    }
}

// ---------------- K3: layer-1 recurrence via HMMA (reads g_xg) ---------------
__global__ __launch_bounds__(512, 1) void k_rec1() {
    __shared__ float  gates[GDIM * GPITCH];
    __shared__ __half hT[8 * 136];

    const int t = threadIdx.x;
    const int warp = t >> 5, lane = t & 31;
    const int g = lane >> 2, tg = lane & 3;

    const __half* Wg = g_whh + GDIM * HDIM;         // layer 1
    unsigned afr[2][8][4];
    #pragma unroll
    for (int mt = 0; mt < 2; mt++) {
        int rbase = warp * 32 + mt * 16;
        #pragma unroll
        for (int kt = 0; kt < 8; kt++) {
            int kb = kt * 16 + tg * 2;
            afr[mt][kt][0] = *(const unsigned*)&Wg[(rbase + g)     * HDIM + kb];
            afr[mt][kt][1] = *(const unsigned*)&Wg[(rbase + g + 8) * HDIM + kb];
            afr[mt][kt][2] = *(const unsigned*)&Wg[(rbase + g)     * HDIM + kb + 8];
            afr[mt][kt][3] = *(const unsigned*)&Wg[(rbase + g + 8) * HDIM + kb + 8];
        }
    }

    for (int i = t; i < 8 * 136; i += 512) hT[i] = __float2half(0.f);

    const int b = t >> 7, u = t & 127;
    float cstate = 0.f;
    const size_t cta_b = (size_t)blockIdx.x * 4;
    const __half* xbase = g_xg + (cta_b + b) * ((size_t)TSTEPS * GDIM) + u;

    __half xc[4];
    xc[0] = xbase[0]; xc[1] = xbase[128]; xc[2] = xbase[256]; xc[3] = xbase[384];
    __syncthreads();

    for (int ts = 0; ts < TSTEPS; ts++) {
        __half xn[4];
        if (ts < TSTEPS - 1) {
            const __half* xp = xbase + (size_t)(ts + 1) * GDIM;
            xn[0] = xp[0]; xn[1] = xp[128]; xn[2] = xp[256]; xn[3] = xp[384];
        }

        float acc[2][4];
        #pragma unroll
        for (int mt = 0; mt < 2; mt++)
            #pragma unroll
            for (int p = 0; p < 4; p++) acc[mt][p] = 0.f;

        #pragma unroll
        for (int kt = 0; kt < 8; kt++) {
            unsigned b0 = *(const unsigned*)&hT[g * 136 + kt * 16 + tg * 2];
            unsigned b1 = *(const unsigned*)&hT[g * 136 + kt * 16 + tg * 2 + 8];
            hmma(acc[0], afr[0][kt], b0, b1);
            hmma(acc[1], afr[1][kt], b0, b1);
        }
        #pragma unroll
        for (int mt = 0; mt < 2; mt++) {
            int r = warp * 32 + mt * 16 + g;
            *(float2*)&gates[r * GPITCH + 2 * tg]       = make_float2(acc[mt][0], acc[mt][1]);
            *(float2*)&gates[(r + 8) * GPITCH + 2 * tg] = make_float2(acc[mt][2], acc[mt][3]);
        }
        __syncthreads();

        {
            int base = u * GPITCH + b;
            float gi = sigmf (gates[base]                + __half2float(xc[0]));
            float gf = sigmf (gates[base + 128 * GPITCH] + __half2float(xc[1]));
            float gg = tanhf_(gates[base + 256 * GPITCH] + __half2float(xc[2]));
            float go = sigmf (gates[base + 384 * GPITCH] + __half2float(xc[3]));
            cstate = gf * cstate + gi * gg;
            float h = go * tanhf_(cstate);
            hT[b * 136 + u] = __float2half(h);
            if (ts == TSTEPS - 1)
                g_h1last[(cta_b + b) * HDIM + u] = h;
        }
        __syncthreads();

        xc[0] = xn[0]; xc[1] = xn[1]; xc[2] = xn[2]; xc[3] = xn[3];
    }
}

// ---------------- K4: FC head -------------------------------------------------
__global__ void k_fc(const float* __restrict__ w1, const float* __restrict__ b1,
                     const float* __restrict__ w2, const float* __restrict__ b2,
                     float* __restrict__ out) {
    __shared__ float red[2];
    int b = blockIdx.x, j = threadIdx.x;   // 64 threads
    const float* hv = g_h1last + b * HDIM;
    const float* wr = w1 + j * HDIM;
    float acc = b1[j];
    #pragma unroll 4
    for (int k = 0; k < HDIM; k++) acc += hv[k] * wr[k];
    float z = fmaxf(acc, 0.0f) * w2[j];
    #pragma unroll
    for (int off = 16; off > 0; off >>= 1) z += __shfl_down_sync(0xffffffffu, z, off);
    if ((j & 31) == 0) red[j >> 5] = z;
    __syncthreads();
    if (j == 0) out[b] = red[0] + red[1] + b2[0];
}

// ---------------- launch -----------------------------------------------------
extern "C" void kernel_launch(void* const* d_in, const int* in_sizes, int n_in,
                              void* d_out, int out_size) {
    const float* x     = (const float*)d_in[0];
    const float* w_ih0 = (const float*)d_in[1];
    const float* w_hh0 = (const float*)d_in[2];
    const float* b_ih0 = (const float*)d_in[3];
    const float* b_hh0 = (const float*)d_in[4];
    const float* w_ih1 = (const float*)d_in[5];
    const float* w_hh1 = (const float*)d_in[6];
    const float* b_ih1 = (const float*)d_in[7];
    const float* b_hh1 = (const float*)d_in[8];
    const float* fc1_w = (const float*)d_in[9];
    const float* fc1_b = (const float*)d_in[10];
    const float* fc2_w = (const float*)d_in[11];
    const float* fc2_b = (const float*)d_in[12];
    float* out = (float*)d_out;

    const int smem_rec0 = 163840 + 20480 + 2176;   // 186496
    cudaFuncSetAttribute(k_rec0, cudaFuncAttributeMaxDynamicSharedMemorySize, smem_rec0);

    // fp16 conversions + bias sums
    k_convert<<<(BATCH * TSTEPS * IDIM + 255) / 256, 256>>>(
        x, w_ih0, w_hh0, b_ih0, b_hh0, w_ih1, w_hh1, b_ih1, b_hh1);
    // layer 0: fused input-GEMM + recurrence (writes g_h0)
    k_rec0<<<128, 512, smem_rec0>>>();
    // xg1 = h0 @ w_ih1^T + bsum1 (HMMA, writes g_xg)
    k_gemmh<<<1024, 512>>>();
    // layer-1 recurrence (writes g_h1last)
    k_rec1<<<128, 512>>>();
    // FC head
    k_fc<<<BATCH, 64>>>(fc1_w, fc1_b, fc2_w, fc2_b, out);
}